// round 3
// baseline (speedup 1.0000x reference)
#include <cuda_runtime.h>
#include <math.h>

#define NBLOCKS 256
#define NTHREADS 256

__device__ float g_partials[NBLOCKS];
__device__ unsigned int g_count = 0;

__global__ void __launch_bounds__(NTHREADS)
smpl_fused_kernel(const float* __restrict__ corr,
                  const float* __restrict__ gt,
                  const float* __restrict__ vis,
                  float* __restrict__ out,
                  int B, int h, int w, float inv_count) {
    const int hw = h * w;
    const int total = B * hw;
    const int stride = gridDim.x * blockDim.x;
    float acc = 0.0f;

    for (int t = blockIdx.x * blockDim.x + threadIdx.x; t < total; t += stride) {
        const int b = t / hw;
        const int p = t - b * hw;

        const float g0 = __ldg(gt + (size_t)b * 2 * hw + p);       // channel 0 -> x
        const float g1 = __ldg(gt + (size_t)b * 2 * hw + hw + p);  // channel 1 -> y
        const float v  = __ldg(vis + (size_t)b * hw + p);

        const float gx = (g0 + 1.0f) * (float)(w - 1) * 0.5f;
        const float gy = (g1 + 1.0f) * (float)(h - 1) * 0.5f;
        const float fx = floorf(gx);
        const float fy = floorf(gy);

        const float wy0 = fy + 1.0f - gy;
        const float wy1 = gy - fy;
        const float wx0 = fx + 1.0f - gx;
        const float wx1 = gx - fx;

        const float wt0 = wy0 * wx0;
        const float wt1 = wy0 * wx1;
        const float wt2 = wy1 * wx0;
        const float wt3 = wy1 * wx1;

        // clamped row/col indices (clip in float then cast, matching reference)
        const float x0f = fminf(fmaxf(fy,        0.0f), (float)(h - 1));
        const float x1f = fminf(fmaxf(fy + 1.0f, 0.0f), (float)(h - 1));
        const float y0f = fminf(fmaxf(fx,        0.0f), (float)(w - 1));
        const float y1f = fminf(fmaxf(fx + 1.0f, 0.0f), (float)(w - 1));
        const int x0 = (int)x0f, x1 = (int)x1f;
        const int y0 = (int)y0f, y1 = (int)y1f;

        const float* __restrict__ row = corr + (size_t)b * hw * hw + (size_t)p * hw;
        const float c0 = __ldg(row + x0 * w + y0);
        const float c1 = __ldg(row + x0 * w + y1);
        const float c2 = __ldg(row + x1 * w + y0);
        const float c3 = __ldg(row + x1 * w + y1);

        acc += fabsf(c0 * v - wt0 * v);
        acc += fabsf(c1 * v - wt1 * v);
        acc += fabsf(c2 * v - wt2 * v);
        acc += fabsf(c3 * v - wt3 * v);
    }

    // Block reduction
    __shared__ float smem[32];
    __shared__ bool is_last;
    const int lane = threadIdx.x & 31;
    const int wid  = threadIdx.x >> 5;
    #pragma unroll
    for (int off = 16; off > 0; off >>= 1)
        acc += __shfl_down_sync(0xFFFFFFFFu, acc, off);
    if (lane == 0) smem[wid] = acc;
    __syncthreads();
    if (wid == 0) {
        float s = (lane < (NTHREADS >> 5)) ? smem[lane] : 0.0f;
        #pragma unroll
        for (int off = 16; off > 0; off >>= 1)
            s += __shfl_down_sync(0xFFFFFFFFu, s, off);
        if (lane == 0) {
            g_partials[blockIdx.x] = s;
            __threadfence();
            unsigned int ticket = atomicAdd(&g_count, 1u);
            is_last = (ticket == gridDim.x - 1);
        }
    }
    __syncthreads();

    // Last block deterministically reduces all partials and resets the counter.
    if (is_last) {
        float a = 0.0f;
        for (int i = threadIdx.x; i < (int)gridDim.x; i += blockDim.x) {
            float p;
            asm volatile("ld.global.cg.f32 %0, [%1];" : "=f"(p) : "l"(g_partials + i));
            a += p;
        }
        #pragma unroll
        for (int off = 16; off > 0; off >>= 1)
            a += __shfl_down_sync(0xFFFFFFFFu, a, off);
        if (lane == 0) smem[wid] = a;
        __syncthreads();
        if (wid == 0) {
            float s = (lane < (NTHREADS >> 5)) ? smem[lane] : 0.0f;
            #pragma unroll
            for (int off = 16; off > 0; off >>= 1)
                s += __shfl_down_sync(0xFFFFFFFFu, s, off);
            if (lane == 0) {
                out[0] = s * inv_count;
                g_count = 0;  // reset for next graph replay
            }
        }
    }
}

extern "C" void kernel_launch(void* const* d_in, const int* in_sizes, int n_in,
                              void* d_out, int out_size) {
    const float* corr = (const float*)d_in[0];  // [B, h*w, h*w]
    const float* gt   = (const float*)d_in[1];  // [B, 2, h, w]
    const float* vis  = (const float*)d_in[2];  // [B, 1, h, w]
    float* out = (float*)d_out;

    const long long n_corr = in_sizes[0];
    const long long n_vis  = in_sizes[2];
    const int hw = (int)(n_corr / n_vis);
    const int B  = (int)(n_vis / hw);
    int h = 1;
    while (h * h < hw) h++;
    const int w = h;

    const int total = B * hw;
    const float inv_count = 1.0f / (4.0f * (float)total);

    smpl_fused_kernel<<<NBLOCKS, NTHREADS>>>(corr, gt, vis, out, B, h, w, inv_count);
}

// round 5
// speedup vs baseline: 1.0332x; 1.0332x over previous
#include <cuda_runtime.h>
#include <math.h>

#define NBLOCKS 256
#define NTHREADS 256

__device__ float g_partials[NBLOCKS];
__device__ unsigned int g_count = 0;

__device__ __forceinline__ float2 ldg_nc2(const float* p) {
    float2 v;
    asm volatile("ld.global.nc.v2.f32 {%0,%1}, [%2];"
                 : "=f"(v.x), "=f"(v.y) : "l"(p));
    return v;
}

__global__ void __launch_bounds__(NTHREADS)
smpl_fused_kernel(const float* __restrict__ corr,
                  const float* __restrict__ gt,
                  const float* __restrict__ vis,
                  float* __restrict__ out,
                  int B, int h, int w, float inv_count) {
    const int hw = h * w;
    const int total = B * hw;
    const int stride = gridDim.x * blockDim.x;
    float acc = 0.0f;

    for (int t = blockIdx.x * blockDim.x + threadIdx.x; t < total; t += stride) {
        const int b = t / hw;
        const int p = t - b * hw;

        const float g0 = __ldg(gt + (size_t)b * 2 * hw + p);       // channel 0 -> x
        const float g1 = __ldg(gt + (size_t)b * 2 * hw + hw + p);  // channel 1 -> y
        const float v  = __ldg(vis + (size_t)b * hw + p);

        const float gx = (g0 + 1.0f) * (float)(w - 1) * 0.5f;
        const float gy = (g1 + 1.0f) * (float)(h - 1) * 0.5f;
        const float fx = floorf(gx);
        const float fy = floorf(gy);

        const float wy0 = fy + 1.0f - gy;
        const float wy1 = gy - fy;
        const float wx0 = fx + 1.0f - gx;
        const float wx1 = gx - fx;

        const float wt0 = wy0 * wx0;
        const float wt1 = wy0 * wx1;
        const float wt2 = wy1 * wx0;
        const float wt3 = wy1 * wx1;

        // clamped row/col indices (clip in float then cast, matching reference)
        const float x0f = fminf(fmaxf(fy,        0.0f), (float)(h - 1));
        const float x1f = fminf(fmaxf(fy + 1.0f, 0.0f), (float)(h - 1));
        const float y0f = fminf(fmaxf(fx,        0.0f), (float)(w - 1));
        const float y1f = fminf(fmaxf(fx + 1.0f, 0.0f), (float)(w - 1));
        const int x0 = (int)x0f, x1 = (int)x1f;
        const int y0 = (int)y0f, y1 = (int)y1f;

        const float* __restrict__ base0 = corr + (size_t)b * hw * hw + (size_t)p * hw + x0 * w;
        const float* __restrict__ base1 = corr + (size_t)b * hw * hw + (size_t)p * hw + x1 * w;

        float c0, c1, c2, c3;
        // Interior fast path: adjacent columns + 8B alignment -> 2x LDG.64
        // (one L1tex wavefront each instead of two).
        if ((y1 == y0 + 1) && ((y0 & 1) == 0)) {
            const float2 a  = ldg_nc2(base0 + y0);
            const float2 bb = ldg_nc2(base1 + y0);
            c0 = a.x; c1 = a.y; c2 = bb.x; c3 = bb.y;
        } else {
            c0 = __ldg(base0 + y0);
            c1 = __ldg(base0 + y1);
            c2 = __ldg(base1 + y0);
            c3 = __ldg(base1 + y1);
        }

        acc += fabsf(c0 * v - wt0 * v);
        acc += fabsf(c1 * v - wt1 * v);
        acc += fabsf(c2 * v - wt2 * v);
        acc += fabsf(c3 * v - wt3 * v);
    }

    // Block reduction
    __shared__ float smem[32];
    __shared__ bool is_last;
    const int lane = threadIdx.x & 31;
    const int wid  = threadIdx.x >> 5;
    #pragma unroll
    for (int off = 16; off > 0; off >>= 1)
        acc += __shfl_down_sync(0xFFFFFFFFu, acc, off);
    if (lane == 0) smem[wid] = acc;
    __syncthreads();
    if (wid == 0) {
        float s = (lane < (NTHREADS >> 5)) ? smem[lane] : 0.0f;
        #pragma unroll
        for (int off = 16; off > 0; off >>= 1)
            s += __shfl_down_sync(0xFFFFFFFFu, s, off);
        if (lane == 0) {
            g_partials[blockIdx.x] = s;
            __threadfence();
            unsigned int ticket = atomicAdd(&g_count, 1u);
            is_last = (ticket == gridDim.x - 1);
        }
    }
    __syncthreads();

    // Last block deterministically reduces all partials and resets the counter.
    if (is_last) {
        float a = 0.0f;
        for (int i = threadIdx.x; i < (int)gridDim.x; i += blockDim.x) {
            float pv;
            asm volatile("ld.global.cg.f32 %0, [%1];" : "=f"(pv) : "l"(g_partials + i));
            a += pv;
        }
        #pragma unroll
        for (int off = 16; off > 0; off >>= 1)
            a += __shfl_down_sync(0xFFFFFFFFu, a, off);
        if (lane == 0) smem[wid] = a;
        __syncthreads();
        if (wid == 0) {
            float s = (lane < (NTHREADS >> 5)) ? smem[lane] : 0.0f;
            #pragma unroll
            for (int off = 16; off > 0; off >>= 1)
                s += __shfl_down_sync(0xFFFFFFFFu, s, off);
            if (lane == 0) {
                out[0] = s * inv_count;
                g_count = 0;  // reset for next graph replay
            }
        }
    }
}

extern "C" void kernel_launch(void* const* d_in, const int* in_sizes, int n_in,
                              void* d_out, int out_size) {
    const float* corr = (const float*)d_in[0];  // [B, h*w, h*w]
    const float* gt   = (const float*)d_in[1];  // [B, 2, h, w]
    const float* vis  = (const float*)d_in[2];  // [B, 1, h, w]
    float* out = (float*)d_out;

    const long long n_corr = in_sizes[0];
    const long long n_vis  = in_sizes[2];
    const int hw = (int)(n_corr / n_vis);
    const int B  = (int)(n_vis / hw);
    int h = 1;
    while (h * h < hw) h++;
    const int w = h;

    const int total = B * hw;
    const float inv_count = 1.0f / (4.0f * (float)total);

    smpl_fused_kernel<<<NBLOCKS, NTHREADS>>>(corr, gt, vis, out, B, h, w, inv_count);
}